// round 16
// baseline (speedup 1.0000x reference)
#include <cuda_runtime.h>
#include <cstdint>

// ---------------------------------------------------------------------------
// Problem constants
// ---------------------------------------------------------------------------
#define T_STEPS 100
#define B_SZ    32
#define NIN     512
#define N_NEU   2048
#define A_AR    2
#define NC      4096                    // A*N output columns, c = a*2048+n
#define KROWS   4608                    // NIN + NC input rows
#define KCHUNK  144                     // 4608 / 32 k-chunks
#define NKC     32                      // number of k-chunks
#define NBY     8                       // k-splits (4 chunks each)
#define NBG     4                       // batch groups of 8
#define XIS_SZ  (T_STEPS * B_SZ * NIN)  // 1,638,400
#define SS_SZ   (T_STEPS * B_SZ * N_NEU)// 6,553,600 per area
// alpha = float32(exp(-0.1))
#define ALPHA_F 0.9048374180359595731642491f

// ---------------------------------------------------------------------------
// Device-global scratch (static — no allocation anywhere).
//   g_mff[t][bg][i] : ff spike mask bytes, rewritten fully every launch.
//   g_rec[bg][c]    : recurrent spike mask bytes for the CURRENT step;
//                     zeroed by mega_prep every launch, rewritten each step.
// All persistent state is rewritten or zeroed every launch (replay-safe).
// ---------------------------------------------------------------------------
__device__ float         g_W[KROWS * NC];              // fused weights [k][c]
__device__ float         g_V[B_SZ * NC];               // membrane V [b][c]
__device__ float         g_P[NBY * B_SZ * NC];         // partials [by][b][c]
__device__ unsigned char g_mff[T_STEPS * NBG * NIN];   // ff masks per t
__device__ unsigned char g_rec[NBG * NC];              // recurrent masks

// ---------------------------------------------------------------------------
// Packed f32x2 helpers (sm_103a) — immune to fast-math contraction
// ---------------------------------------------------------------------------
__device__ __forceinline__ unsigned long long pack2(unsigned lo, unsigned hi) {
    unsigned long long d;
    asm("mov.b64 %0, {%1, %2};" : "=l"(d) : "r"(lo), "r"(hi));
    return d;
}
__device__ __forceinline__ unsigned long long ffma2(unsigned long long a,
                                                    unsigned long long b,
                                                    unsigned long long c) {
    unsigned long long d;
    asm("fma.rn.f32x2 %0, %1, %2, %3;" : "=l"(d) : "l"(a), "l"(b), "l"(c));
    return d;
}
__device__ __forceinline__ unsigned long long fadd2(unsigned long long a,
                                                    unsigned long long b) {
    unsigned long long d;
    asm("add.rn.f32x2 %0, %1, %2;" : "=l"(d) : "l"(a), "l"(b));
    return d;
}
__device__ __forceinline__ float lo32(unsigned long long v) {
    return __uint_as_float((unsigned)v);
}
__device__ __forceinline__ float hi32(unsigned long long v) {
    return __uint_as_float((unsigned)(v >> 32));
}

// ---------------------------------------------------------------------------
// Kernel 1 (the ONLY prep launch): three independent grid-stride jobs,
// all deterministic and atomic-free.
//  A) One thread per (t, bg, i): computes the 8 batch spikes, writes the 8
//     output floats (Xis region, [t][b][i]) and the g_mff byte.
//  B) Fuse Win [A,NIN,N] + Wrec [S,A,N,N] into g_W[k][c].
//  C) Zero V and g_rec (fresh state every launch/replay).
// ---------------------------------------------------------------------------
__global__ void __launch_bounds__(256) mega_prep(const float* __restrict__ rates,
                                                 const float* __restrict__ noise,
                                                 const float* __restrict__ Win,
                                                 const float* __restrict__ Wrec,
                                                 float* __restrict__ out) {
    const int gsz  = gridDim.x * blockDim.x;
    const int tid0 = blockIdx.x * blockDim.x + threadIdx.x;

    // ---- Job A: spikes + ff mask bytes ----
    const int na = T_STEPS * NBG * NIN;
    for (int idx = tid0; idx < na; idx += gsz) {
        int t  = idx / (NBG * NIN);
        int r  = idx - t * (NBG * NIN);
        int bg = r >> 9;               // / NIN
        int i  = r & (NIN - 1);
        unsigned m = 0;
#pragma unroll
        for (int b8 = 0; b8 < 8; b8++) {
            int e = (t * B_SZ + bg * 8 + b8) * NIN + i;
            float rt = rates[e];
            float nz = noise[e];
            bool sp = nz < __fmul_rn(rt, 1e-3f);
            out[e] = sp ? 1.0f : 0.0f;
            m |= (sp ? 1u : 0u) << b8;
        }
        g_mff[idx] = (unsigned char)m;
    }

    // ---- Job B: pack W ----
    const int total4 = KROWS * NC / 4;
    for (int idx = tid0; idx < total4; idx += gsz) {
        int e = idx << 2;
        int k = e >> 12;              // / 4096
        int c = e & (NC - 1);
        int a = c >> 11;
        int n = c & (N_NEU - 1);
        float4 v;
        if (k < NIN) {
            v = *(const float4*)&Win[(a * NIN + k) * N_NEU + n];
        } else {
            int kr = k - NIN;
            int s  = kr >> 11;
            int m  = kr & (N_NEU - 1);
            v = *(const float4*)&Wrec[(((s * A_AR + a) * N_NEU) + m) * (size_t)N_NEU + n];
        }
        *(float4*)&g_W[e] = v;
    }

    // ---- Job C: zero V + recurrent masks ----
    for (int idx = tid0; idx < B_SZ * NC; idx += gsz) g_V[idx] = 0.0f;
    for (int idx = tid0; idx < NBG * NC / 4; idx += gsz)
        ((unsigned*)g_rec)[idx] = 0u;
}

// ---------------------------------------------------------------------------
// Kernel B (per step): mask-driven compact + sparse binary-spike GEMM.
// BYTE-IDENTICAL to the R14 passing kernel (4 blocks/SM, single wave).
// Grid: (16 col-tiles, 4 bg, 8 by). Block: 8 warps = 4 ksub x 2 cw.
// ---------------------------------------------------------------------------
struct SmemP1 {
    unsigned list[4][KCHUNK];       // W byte offsets (k * NC * 4), ascending
    float    spk[4][KCHUNK][8];     // expanded spike floats
    int      cnt[4];
};
union SmemU {
    SmemP1 p1;
    unsigned long long sbuf[8][32][17];   // reduce buffer (16 u64 + pad)
};

__device__ __forceinline__ void fma_row(unsigned long long acc[4][4],
                                        float4 wv, const float* __restrict__ sp) {
    float4 sA = *(const float4*)sp;
    float4 sB = *(const float4*)(sp + 4);
    unsigned long long s2[4];
    s2[0] = pack2(__float_as_uint(sA.x), __float_as_uint(sA.y));
    s2[1] = pack2(__float_as_uint(sA.z), __float_as_uint(sA.w));
    s2[2] = pack2(__float_as_uint(sB.x), __float_as_uint(sB.y));
    s2[3] = pack2(__float_as_uint(sB.z), __float_as_uint(sB.w));
    unsigned wb[4] = {__float_as_uint(wv.x), __float_as_uint(wv.y),
                      __float_as_uint(wv.z), __float_as_uint(wv.w)};
#pragma unroll
    for (int c = 0; c < 4; c++) {
        unsigned long long w2 = pack2(wb[c], wb[c]);
#pragma unroll
        for (int j = 0; j < 4; j++)
            acc[c][j] = ffma2(w2, s2[j], acc[c][j]);
    }
}

__global__ void __launch_bounds__(256, 4) step_gemm(int t) {
    __shared__ SmemU sm;

    const int tid  = threadIdx.x;
    const int w    = tid >> 5;
    const int lane = tid & 31;
    const int cw   = w & 1;          // column half within block
    const int ksub = w >> 1;         // 0..3
    const int bg   = blockIdx.y;     // batch group (8 batches)
    const int by   = blockIdx.z;     // partial index
    const int c0   = blockIdx.x * 256 + cw * 128 + lane * 4;

    // ---- Phase 1: warps 0..3 compact chunk (by*4 + w) for this bg ----
    if (w < 4) {
        const int kc = by * 4 + w;
        const int k0 = kc * KCHUNK;
        const unsigned char* __restrict__ mff_t = &g_mff[(t * NBG + bg) * NIN];
        const unsigned char* __restrict__ recb  = &g_rec[bg * NC];
        int total = 0;
#pragma unroll
        for (int it = 0; it < 5; it++) {
            int r = it * 32 + lane;
            int k = k0 + r;
            unsigned msk = 0u;
            if (r < KCHUNK)
                msk = (k < NIN) ? (unsigned)mff_t[k] : (unsigned)recb[k - NIN];
            bool act = msk != 0u;
            unsigned bal = __ballot_sync(0xFFFFFFFFu, act);
            if (act) {
                int pos = total + __popc(bal & ((1u << lane) - 1u));
                sm.p1.list[w][pos] = (unsigned)k * (NC * 4);
#pragma unroll
                for (int b = 0; b < 8; b++)
                    sm.p1.spk[w][pos][b] = (msk >> b) & 1u ? 1.0f : 0.0f;
            }
            total += __popc(bal);
        }
        if (lane == 0) sm.p1.cnt[w] = total;
    }
    __syncthreads();

    // ---- Phase 2: sparse FMA loop, 2-row batched W prefetch ----
    const int n = sm.p1.cnt[ksub];
    const unsigned* __restrict__ lst = sm.p1.list[ksub];
    const float*    __restrict__ spk = &sm.p1.spk[ksub][0][0];
    const char* __restrict__ wbase = (const char*)g_W + (unsigned)c0 * 4u;

    unsigned long long acc[4][4];
#pragma unroll
    for (int c = 0; c < 4; c++)
#pragma unroll
        for (int j = 0; j < 4; j++) acc[c][j] = 0ull;

    int i = 0;
    for (; i + 2 <= n; i += 2) {
        uint2 off = *(const uint2*)&lst[i];           // one LDS.64: 2 offsets
        float4 wv0 = *(const float4*)(wbase + off.x); // 2 independent LDG.128
        float4 wv1 = *(const float4*)(wbase + off.y);
        fma_row(acc, wv0, &spk[(i + 0) * 8]);
        fma_row(acc, wv1, &spk[(i + 1) * 8]);
    }
    for (; i < n; i++) {
        unsigned off = lst[i];
        float4 wv = *(const float4*)(wbase + off);
        fma_row(acc, wv, &spk[i * 8]);
    }

    __syncthreads();   // phase-1 data consumed; safe to reuse shared

#pragma unroll
    for (int c = 0; c < 4; c++)
#pragma unroll
        for (int j = 0; j < 4; j++) sm.sbuf[w][lane][c * 4 + j] = acc[c][j];
    __syncthreads();

    if (ksub == 0) {
#pragma unroll
        for (int ks = 1; ks < 4; ks++) {
#pragma unroll
            for (int c = 0; c < 4; c++)
#pragma unroll
                for (int j = 0; j < 4; j++)
                    acc[c][j] = fadd2(acc[c][j], sm.sbuf[ks * 2 + cw][lane][c * 4 + j]);
        }
        // transposed, coalesced stores: g_P[by][b][c0..c0+3]
#pragma unroll
        for (int j = 0; j < 4; j++) {
            int b = bg * 8 + 2 * j;
            float4 lo4 = make_float4(lo32(acc[0][j]), lo32(acc[1][j]),
                                     lo32(acc[2][j]), lo32(acc[3][j]));
            float4 hi4 = make_float4(hi32(acc[0][j]), hi32(acc[1][j]),
                                     hi32(acc[2][j]), hi32(acc[3][j]));
            *(float4*)&g_P[(unsigned)((by * B_SZ + b)     * NC) + c0] = lo4;
            *(float4*)&g_P[(unsigned)((by * B_SZ + b + 1) * NC) + c0] = hi4;
        }
    }
}

// ---------------------------------------------------------------------------
// Kernel C (per step): ONE (batch, neuron) work-item per thread.
// 131072 threads (512 blocks). Thread gidx: b8 = gidx & 7 (batch in group),
// idx = gidx >> 3 = (bg, c). Lanes 8g..8g+7 of a warp are the 8 batches of
// one (bg, c), so the recurrent mask byte is assembled with one ballot.
// Per (b, c) the arithmetic is BYTE-IDENTICAL to R14: ascending by-fold of 8
// partials, same LIF expression, same threshold, same mask-byte value.
// ---------------------------------------------------------------------------
__global__ void __launch_bounds__(256) step_update(float* __restrict__ out, int t) {
    int gidx = blockIdx.x * blockDim.x + threadIdx.x;   // 0 .. 131071
    if (gidx >= NBG * NC * 8) return;
    int b8  = gidx & 7;
    int idx = gidx >> 3;          // (bg, c)
    int bg  = idx >> 12;
    int c   = idx & (NC - 1);
    int a   = c >> 11;
    int n   = c & (N_NEU - 1);
    int b   = bg * 8 + b8;

    // ascending by-fold — identical sequence per (b, c)
    float I = g_P[(0 * B_SZ + b) * NC + c];
#pragma unroll
    for (int by = 1; by < NBY; by++)
        I = __fadd_rn(I, g_P[(by * B_SZ + b) * NC + c]);

    unsigned oldm = g_rec[idx];
    float xd   = (oldm >> b8) & 1u ? 1.0f : 0.0f;
    float Vold = g_V[b * NC + c];
    float Vnew = __fadd_rn(__fmul_rn(__fmul_rn(ALPHA_F, Vold),
                                     __fsub_rn(1.0f, xd)), I);
    unsigned s = Vnew >= 1.0f ? 1u : 0u;
    g_V[b * NC + c] = Vnew;
    out[XIS_SZ + a * SS_SZ + t * (B_SZ * N_NEU) + b * N_NEU + n] =
        s ? 1.0f : 0.0f;

    // assemble the 8-batch mask byte from this lane group
    unsigned bal = __ballot_sync(0xFFFFFFFFu, s != 0u);
    if (b8 == 0) {
        unsigned grp = (threadIdx.x & 31) & 24u;        // 8*(lane/8)
        g_rec[idx] = (unsigned char)((bal >> grp) & 0xFFu);
    }
}

// ---------------------------------------------------------------------------
// Launch: 1 prep kernel + 100 x (gemm, update). Graph-capturable, replay-
// deterministic (all persistent state rewritten or zeroed each call).
// ---------------------------------------------------------------------------
extern "C" void kernel_launch(void* const* d_in, const int* in_sizes, int n_in,
                              void* d_out, int out_size) {
    const float* rates = (const float*)d_in[0];
    const float* noise = (const float*)d_in[1];
    const float* Win   = (const float*)d_in[2];
    const float* Wrec  = (const float*)d_in[3];
    float* out = (float*)d_out;

    mega_prep<<<2048, 256>>>(rates, noise, Win, Wrec, out);

    for (int t = 0; t < T_STEPS; t++) {
        step_gemm<<<dim3(16, NBG, NBY), 256>>>(t);
        step_update<<<(NBG * NC * 8) / 256, 256>>>(out, t);
    }
}

// round 17
// speedup vs baseline: 1.4866x; 1.4866x over previous
#include <cuda_runtime.h>
#include <cstdint>

// ---------------------------------------------------------------------------
// Problem constants
// ---------------------------------------------------------------------------
#define T_STEPS 100
#define B_SZ    32
#define NIN     512
#define N_NEU   2048
#define A_AR    2
#define NC      4096                    // A*N output columns, c = a*2048+n
#define KROWS   4608                    // NIN + NC input rows
#define KCHUNK  144                     // 4608 / 32 k-chunks
#define NKC     32                      // number of k-chunks
#define NBY     8                       // k-splits (4 chunks each)
#define NBG     4                       // batch groups of 8
#define XIS_SZ  (T_STEPS * B_SZ * NIN)  // 1,638,400
#define SS_SZ   (T_STEPS * B_SZ * N_NEU)// 6,553,600 per area
// alpha = float32(exp(-0.1))
#define ALPHA_F 0.9048374180359595731642491f

// ---------------------------------------------------------------------------
// Device-global scratch (static — no allocation anywhere).
//   g_mff[t][bg][i]    : ff spike mask bytes (rewritten fully every launch)
//   g_rec[bg][c]       : recurrent spike mask bytes (zeroed every launch)
//   g_P[by][bg][c][b8] : partials, 8 floats contiguous per (bg, c)
//   g_V2[bg][c][b8]    : membrane V, same (bg, c, b8) layout
// All persistent state is rewritten or zeroed every launch (replay-safe).
// ---------------------------------------------------------------------------
__device__ float         g_W[KROWS * NC];              // fused weights [k][c]
__device__ float         g_V2[NBG * NC * 8];           // membrane V [bg][c][b8]
__device__ float         g_P[NBY * NBG * NC * 8];      // partials [by][bg][c][b8]
__device__ unsigned char g_mff[T_STEPS * NBG * NIN];   // ff masks per t
__device__ unsigned char g_rec[NBG * NC];              // recurrent masks

// ---------------------------------------------------------------------------
// Packed f32x2 helpers (sm_103a) — immune to fast-math contraction
// ---------------------------------------------------------------------------
__device__ __forceinline__ unsigned long long pack2(unsigned lo, unsigned hi) {
    unsigned long long d;
    asm("mov.b64 %0, {%1, %2};" : "=l"(d) : "r"(lo), "r"(hi));
    return d;
}
__device__ __forceinline__ unsigned long long ffma2(unsigned long long a,
                                                    unsigned long long b,
                                                    unsigned long long c) {
    unsigned long long d;
    asm("fma.rn.f32x2 %0, %1, %2, %3;" : "=l"(d) : "l"(a), "l"(b), "l"(c));
    return d;
}
__device__ __forceinline__ unsigned long long fadd2(unsigned long long a,
                                                    unsigned long long b) {
    unsigned long long d;
    asm("add.rn.f32x2 %0, %1, %2;" : "=l"(d) : "l"(a), "l"(b));
    return d;
}
__device__ __forceinline__ float lo32(unsigned long long v) {
    return __uint_as_float((unsigned)v);
}
__device__ __forceinline__ float hi32(unsigned long long v) {
    return __uint_as_float((unsigned)(v >> 32));
}

// ---------------------------------------------------------------------------
// Kernel 1 (the ONLY prep launch): three independent grid-stride jobs,
// all deterministic and atomic-free.
//  A) One thread per (t, bg, i): computes the 8 batch spikes, writes the 8
//     output floats (Xis region, [t][b][i]) and the g_mff byte.
//  B) Fuse Win [A,NIN,N] + Wrec [S,A,N,N] into g_W[k][c].
//  C) Zero V2 and g_rec (fresh state every launch/replay).
// ---------------------------------------------------------------------------
__global__ void __launch_bounds__(256) mega_prep(const float* __restrict__ rates,
                                                 const float* __restrict__ noise,
                                                 const float* __restrict__ Win,
                                                 const float* __restrict__ Wrec,
                                                 float* __restrict__ out) {
    const int gsz  = gridDim.x * blockDim.x;
    const int tid0 = blockIdx.x * blockDim.x + threadIdx.x;

    // ---- Job A: spikes + ff mask bytes ----
    const int na = T_STEPS * NBG * NIN;
    for (int idx = tid0; idx < na; idx += gsz) {
        int t  = idx / (NBG * NIN);
        int r  = idx - t * (NBG * NIN);
        int bg = r >> 9;               // / NIN
        int i  = r & (NIN - 1);
        unsigned m = 0;
#pragma unroll
        for (int b8 = 0; b8 < 8; b8++) {
            int e = (t * B_SZ + bg * 8 + b8) * NIN + i;
            float rt = rates[e];
            float nz = noise[e];
            bool sp = nz < __fmul_rn(rt, 1e-3f);
            out[e] = sp ? 1.0f : 0.0f;
            m |= (sp ? 1u : 0u) << b8;
        }
        g_mff[idx] = (unsigned char)m;
    }

    // ---- Job B: pack W ----
    const int total4 = KROWS * NC / 4;
    for (int idx = tid0; idx < total4; idx += gsz) {
        int e = idx << 2;
        int k = e >> 12;              // / 4096
        int c = e & (NC - 1);
        int a = c >> 11;
        int n = c & (N_NEU - 1);
        float4 v;
        if (k < NIN) {
            v = *(const float4*)&Win[(a * NIN + k) * N_NEU + n];
        } else {
            int kr = k - NIN;
            int s  = kr >> 11;
            int m  = kr & (N_NEU - 1);
            v = *(const float4*)&Wrec[(((s * A_AR + a) * N_NEU) + m) * (size_t)N_NEU + n];
        }
        *(float4*)&g_W[e] = v;
    }

    // ---- Job C: zero V2 + recurrent masks ----
    for (int idx = tid0; idx < NBG * NC * 8; idx += gsz) g_V2[idx] = 0.0f;
    for (int idx = tid0; idx < NBG * NC / 4; idx += gsz)
        ((unsigned*)g_rec)[idx] = 0u;
}

// ---------------------------------------------------------------------------
// Kernel B (per step): mask-driven compact + sparse binary-spike GEMM.
// Compute is BYTE-IDENTICAL to the R14 passing kernel (4 blocks/SM, single
// wave). Grid: (16 col-tiles, 4 bg, 8 by). Block: 8 warps = 4 ksub x 2 cw.
// Only the epilogue STORE ADDRESSES changed (g_P[by][bg][c][b8] layout):
// each lane writes its 4 c's as 2 float4 each -> 128B contiguous per lane,
// fully coalesced.
// ---------------------------------------------------------------------------
struct SmemP1 {
    unsigned list[4][KCHUNK];       // W byte offsets (k * NC * 4), ascending
    float    spk[4][KCHUNK][8];     // expanded spike floats
    int      cnt[4];
};
union SmemU {
    SmemP1 p1;
    unsigned long long sbuf[8][32][17];   // reduce buffer (16 u64 + pad)
};

__device__ __forceinline__ void fma_row(unsigned long long acc[4][4],
                                        float4 wv, const float* __restrict__ sp) {
    float4 sA = *(const float4*)sp;
    float4 sB = *(const float4*)(sp + 4);
    unsigned long long s2[4];
    s2[0] = pack2(__float_as_uint(sA.x), __float_as_uint(sA.y));
    s2[1] = pack2(__float_as_uint(sA.z), __float_as_uint(sA.w));
    s2[2] = pack2(__float_as_uint(sB.x), __float_as_uint(sB.y));
    s2[3] = pack2(__float_as_uint(sB.z), __float_as_uint(sB.w));
    unsigned wb[4] = {__float_as_uint(wv.x), __float_as_uint(wv.y),
                      __float_as_uint(wv.z), __float_as_uint(wv.w)};
#pragma unroll
    for (int c = 0; c < 4; c++) {
        unsigned long long w2 = pack2(wb[c], wb[c]);
#pragma unroll
        for (int j = 0; j < 4; j++)
            acc[c][j] = ffma2(w2, s2[j], acc[c][j]);
    }
}

__global__ void __launch_bounds__(256, 4) step_gemm(int t) {
    __shared__ SmemU sm;

    const int tid  = threadIdx.x;
    const int w    = tid >> 5;
    const int lane = tid & 31;
    const int cw   = w & 1;          // column half within block
    const int ksub = w >> 1;         // 0..3
    const int bg   = blockIdx.y;     // batch group (8 batches)
    const int by   = blockIdx.z;     // partial index
    const int c0   = blockIdx.x * 256 + cw * 128 + lane * 4;

    // ---- Phase 1: warps 0..3 compact chunk (by*4 + w) for this bg ----
    if (w < 4) {
        const int kc = by * 4 + w;
        const int k0 = kc * KCHUNK;
        const unsigned char* __restrict__ mff_t = &g_mff[(t * NBG + bg) * NIN];
        const unsigned char* __restrict__ recb  = &g_rec[bg * NC];
        int total = 0;
#pragma unroll
        for (int it = 0; it < 5; it++) {
            int r = it * 32 + lane;
            int k = k0 + r;
            unsigned msk = 0u;
            if (r < KCHUNK)
                msk = (k < NIN) ? (unsigned)mff_t[k] : (unsigned)recb[k - NIN];
            bool act = msk != 0u;
            unsigned bal = __ballot_sync(0xFFFFFFFFu, act);
            if (act) {
                int pos = total + __popc(bal & ((1u << lane) - 1u));
                sm.p1.list[w][pos] = (unsigned)k * (NC * 4);
#pragma unroll
                for (int b = 0; b < 8; b++)
                    sm.p1.spk[w][pos][b] = (msk >> b) & 1u ? 1.0f : 0.0f;
            }
            total += __popc(bal);
        }
        if (lane == 0) sm.p1.cnt[w] = total;
    }
    __syncthreads();

    // ---- Phase 2: sparse FMA loop, 2-row batched W prefetch ----
    const int n = sm.p1.cnt[ksub];
    const unsigned* __restrict__ lst = sm.p1.list[ksub];
    const float*    __restrict__ spk = &sm.p1.spk[ksub][0][0];
    const char* __restrict__ wbase = (const char*)g_W + (unsigned)c0 * 4u;

    unsigned long long acc[4][4];
#pragma unroll
    for (int c = 0; c < 4; c++)
#pragma unroll
        for (int j = 0; j < 4; j++) acc[c][j] = 0ull;

    int i = 0;
    for (; i + 2 <= n; i += 2) {
        uint2 off = *(const uint2*)&lst[i];           // one LDS.64: 2 offsets
        float4 wv0 = *(const float4*)(wbase + off.x); // 2 independent LDG.128
        float4 wv1 = *(const float4*)(wbase + off.y);
        fma_row(acc, wv0, &spk[(i + 0) * 8]);
        fma_row(acc, wv1, &spk[(i + 1) * 8]);
    }
    for (; i < n; i++) {
        unsigned off = lst[i];
        float4 wv = *(const float4*)(wbase + off);
        fma_row(acc, wv, &spk[i * 8]);
    }

    __syncthreads();   // phase-1 data consumed; safe to reuse shared

#pragma unroll
    for (int c = 0; c < 4; c++)
#pragma unroll
        for (int j = 0; j < 4; j++) sm.sbuf[w][lane][c * 4 + j] = acc[c][j];
    __syncthreads();

    if (ksub == 0) {
#pragma unroll
        for (int ks = 1; ks < 4; ks++) {
#pragma unroll
            for (int c = 0; c < 4; c++)
#pragma unroll
                for (int j = 0; j < 4; j++)
                    acc[c][j] = fadd2(acc[c][j], sm.sbuf[ks * 2 + cw][lane][c * 4 + j]);
        }
        // stores to g_P[by][bg][c][b8]: per c, 8 contiguous floats (2 x STG.128)
#pragma unroll
        for (int cc = 0; cc < 4; cc++) {
            float4 v0 = make_float4(lo32(acc[cc][0]), hi32(acc[cc][0]),
                                    lo32(acc[cc][1]), hi32(acc[cc][1]));
            float4 v1 = make_float4(lo32(acc[cc][2]), hi32(acc[cc][2]),
                                    lo32(acc[cc][3]), hi32(acc[cc][3]));
            unsigned base = (unsigned)(((by * NBG + bg) * NC) + c0 + cc) * 8u;
            *(float4*)&g_P[base]     = v0;
            *(float4*)&g_P[base + 4] = v1;
        }
    }
}

// ---------------------------------------------------------------------------
// Kernel C (per step): thread = (bg, c) — R14's proven warp shape (c
// contiguous within the warp). With the [by][bg][c][b8] layout each thread's
// 8 partial vectors are 32B contiguous & warp-coalesced: 16 float4 loads,
// all independent (one latency round). V in matching layout (2+2 float4).
// Per (b, c) arithmetic BYTE-IDENTICAL to R14: ascending by-fold, same LIF,
// same threshold, same mask byte (assembled locally, no ballot).
// ---------------------------------------------------------------------------
__global__ void __launch_bounds__(256) step_update(float* __restrict__ out, int t) {
    int idx = blockIdx.x * blockDim.x + threadIdx.x;   // 0 .. 16383
    if (idx >= NBG * NC) return;
    int bg = idx >> 12;
    int c  = idx & (NC - 1);
    int a  = c >> 11;
    int n  = c & (N_NEU - 1);

    // load all 8 by-vectors (8 x 32B, independent)
    float4 p0[NBY], p1[NBY];
#pragma unroll
    for (int by = 0; by < NBY; by++) {
        unsigned base = (unsigned)(((by * NBG + bg) * NC) + c) * 8u;
        p0[by] = *(const float4*)&g_P[base];
        p1[by] = *(const float4*)&g_P[base + 4];
    }

    // ascending by-fold, componentwise (identical per-(b,c) add sequence)
    float4 I0 = p0[0], I1 = p1[0];
#pragma unroll
    for (int by = 1; by < NBY; by++) {
        I0.x = __fadd_rn(I0.x, p0[by].x);
        I0.y = __fadd_rn(I0.y, p0[by].y);
        I0.z = __fadd_rn(I0.z, p0[by].z);
        I0.w = __fadd_rn(I0.w, p0[by].w);
        I1.x = __fadd_rn(I1.x, p1[by].x);
        I1.y = __fadd_rn(I1.y, p1[by].y);
        I1.z = __fadd_rn(I1.z, p1[by].z);
        I1.w = __fadd_rn(I1.w, p1[by].w);
    }
    float I[8] = {I0.x, I0.y, I0.z, I0.w, I1.x, I1.y, I1.z, I1.w};

    float4 V0 = *(const float4*)&g_V2[(unsigned)idx * 8u];
    float4 V1 = *(const float4*)&g_V2[(unsigned)idx * 8u + 4u];
    float V[8] = {V0.x, V0.y, V0.z, V0.w, V1.x, V1.y, V1.z, V1.w};

    unsigned oldm = g_rec[idx];
    unsigned newm = 0;
    float Vn[8];

#pragma unroll
    for (int b8 = 0; b8 < 8; b8++) {
        float xd = (oldm >> b8) & 1u ? 1.0f : 0.0f;
        float Vnew = __fadd_rn(__fmul_rn(__fmul_rn(ALPHA_F, V[b8]),
                                         __fsub_rn(1.0f, xd)), I[b8]);
        unsigned s = Vnew >= 1.0f ? 1u : 0u;
        Vn[b8] = Vnew;
        newm |= s << b8;
        int b = bg * 8 + b8;
        out[XIS_SZ + a * SS_SZ + t * (B_SZ * N_NEU) + b * N_NEU + n] =
            s ? 1.0f : 0.0f;
    }

    *(float4*)&g_V2[(unsigned)idx * 8u]      = make_float4(Vn[0], Vn[1], Vn[2], Vn[3]);
    *(float4*)&g_V2[(unsigned)idx * 8u + 4u] = make_float4(Vn[4], Vn[5], Vn[6], Vn[7]);
    g_rec[idx] = (unsigned char)newm;
}

// ---------------------------------------------------------------------------
// Launch: 1 prep kernel + 100 x (gemm, update). Graph-capturable, replay-
// deterministic (all persistent state rewritten or zeroed each call).
// ---------------------------------------------------------------------------
extern "C" void kernel_launch(void* const* d_in, const int* in_sizes, int n_in,
                              void* d_out, int out_size) {
    const float* rates = (const float*)d_in[0];
    const float* noise = (const float*)d_in[1];
    const float* Win   = (const float*)d_in[2];
    const float* Wrec  = (const float*)d_in[3];
    float* out = (float*)d_out;

    mega_prep<<<2048, 256>>>(rates, noise, Win, Wrec, out);

    for (int t = 0; t < T_STEPS; t++) {
        step_gemm<<<dim3(16, NBG, NBY), 256>>>(t);
        step_update<<<(NBG * NC) / 256, 256>>>(out, t);
    }
}